// round 9
// baseline (speedup 1.0000x reference)
#include <cuda_runtime.h>

// S=64, B=128, D=10000 fixed by the reference.
#define D_DIM   10000
#define D4      2500
#define J_FULL  78            // 78*32 = 2496 float4; tail = 4 (lane<4)
#define S_DIM   64
#define B_DIM   128
#define THREADS 512
#define NWARPS  16
#define NCTAS   256           // (b, half) pairs
#define SMEM_BYTES (2 * D_DIM * sizeof(float))   // 80000 B

#define L2E 1.4426950408889634f

__device__ float    g_partial[NCTAS];
__device__ unsigned g_ticket;      // zero-init; reset by last CTA each launch

__device__ __forceinline__ float ex2f(float x) {
    float r;
    asm("ex2.approx.ftz.f32 %0, %1;" : "=f"(r) : "f"(x));
    return r;
}

// consume one quad (noise n, theta*log2e t, y yv) into one sample's accumulators
__device__ __forceinline__ void consume1(const float4& n, const float4& t,
                                         const float4& yv,
                                         float& sq, float& sq2, float& sqy)
{
    float qx = ex2f(fmaf(n.x, L2E, t.x));
    float qy = ex2f(fmaf(n.y, L2E, t.y));
    float qz = ex2f(fmaf(n.z, L2E, t.z));
    float qw = ex2f(fmaf(n.w, L2E, t.w));
    sq  += (qx + qy) + (qz + qw);
    sq2 = fmaf(qx, qx, sq2);   sq2 = fmaf(qy, qy, sq2);
    sq2 = fmaf(qz, qz, sq2);   sq2 = fmaf(qw, qw, sq2);
    sqy = fmaf(qx, yv.x, sqy); sqy = fmaf(qy, yv.y, sqy);
    sqy = fmaf(qz, yv.z, sqy); sqy = fmaf(qw, yv.w, sqy);
}

__global__ __launch_bounds__(THREADS, 2)
void pl_fused(const float* __restrict__ theta,
              const float* __restrict__ y,
              const float* __restrict__ noise,
              float* __restrict__ out)
{
    extern __shared__ float sm[];          // [0,10000): theta_b*log2e  [10000,20000): y_b
    float* __restrict__ sth = sm;
    float* __restrict__ syy = sm + D_DIM;
    __shared__ float fin[NWARPS];
    __shared__ float s_sy2;
    __shared__ int   is_last;

    const int bid  = blockIdx.x;
    const int b    = bid & (B_DIM - 1);    // batch column
    const int h    = bid >> 7;             // sample half: 0 or 1
    const int tid  = threadIdx.x;
    const int lane = tid & 31;
    const int warp = tid >> 5;

    // ---- stage theta_b*log2e, y_b into shared; exact fp32 Sigma(y^2) ----
    float sy2p = 0.0f;
    {
        const float4* __restrict__ th4 = (const float4*)(theta + (size_t)b * D_DIM);
        const float4* __restrict__ yy4 = (const float4*)(y     + (size_t)b * D_DIM);
        float4* s_t = (float4*)sth;
        float4* s_y = (float4*)syy;
        for (int i = tid; i < D4; i += THREADS) {
            float4 t = __ldg(th4 + i);
            float4 v = __ldg(yy4 + i);
            sy2p = fmaf(v.x, v.x, sy2p);
            sy2p = fmaf(v.y, v.y, sy2p);
            sy2p = fmaf(v.z, v.z, sy2p);
            sy2p = fmaf(v.w, v.w, sy2p);
            t.x *= L2E; t.y *= L2E; t.z *= L2E; t.w *= L2E;
            s_t[i] = t;
            s_y[i] = v;
        }
    }
    #pragma unroll
    for (int o = 16; o; o >>= 1) sy2p += __shfl_xor_sync(0xffffffffu, sy2p, o);
    if (lane == 0) fin[warp] = sy2p;
    __syncthreads();
    if (tid == 0) {
        float t = fin[0];
        #pragma unroll
        for (int w = 1; w < NWARPS; w++) t += fin[w];
        s_sy2 = t;
    }
    __syncthreads();
    const float sy2 = s_sy2;

    const float4* __restrict__ st4 = (const float4*)sth;
    const float4* __restrict__ sy4 = (const float4*)syy;

    // ---- warp interleaves samples sA = h*32 + warp, sB = sA + 16 ----
    const int sA = h * 32 + warp;
    const float4* __restrict__ nzA =
        (const float4*)(noise + ((size_t)sA        * B_DIM + b) * D_DIM);
    const float4* __restrict__ nzB =
        (const float4*)(noise + ((size_t)(sA + 16) * B_DIM + b) * D_DIM);

    float aq = 0.0f, aq2 = 0.0f, aqy = 0.0f;   // sample A accumulators
    float bq = 0.0f, bq2 = 0.0f, bqy = 0.0f;   // sample B accumulators

    // rotating 3-deep pipeline per sample
    float4 A0 = __ldcs(nzA + 0 * 32 + lane);
    float4 B0 = __ldcs(nzB + 0 * 32 + lane);
    float4 A1 = __ldcs(nzA + 1 * 32 + lane);
    float4 B1 = __ldcs(nzB + 1 * 32 + lane);
    float4 A2 = __ldcs(nzA + 2 * 32 + lane);
    float4 B2 = __ldcs(nzB + 2 * 32 + lane);

    // 25 blocks: consume j=jj..jj+2, prefetch jj+3..jj+5 (last prefetch = 75,76,77)
    #pragma unroll 1
    for (int jj = 0; jj <= 72; jj += 3) {
        {
            const int idx = jj * 32 + lane;
            float4 t = st4[idx], yv = sy4[idx];
            consume1(A0, t, yv, aq, aq2, aqy);
            consume1(B0, t, yv, bq, bq2, bqy);
            A0 = __ldcs(nzA + idx + 3 * 32);
            B0 = __ldcs(nzB + idx + 3 * 32);
        }
        {
            const int idx = (jj + 1) * 32 + lane;
            float4 t = st4[idx], yv = sy4[idx];
            consume1(A1, t, yv, aq, aq2, aqy);
            consume1(B1, t, yv, bq, bq2, bqy);
            A1 = __ldcs(nzA + idx + 3 * 32);
            B1 = __ldcs(nzB + idx + 3 * 32);
        }
        {
            const int idx = (jj + 2) * 32 + lane;
            float4 t = st4[idx], yv = sy4[idx];
            consume1(A2, t, yv, aq, aq2, aqy);
            consume1(B2, t, yv, bq, bq2, bqy);
            A2 = __ldcs(nzA + idx + 3 * 32);
            B2 = __ldcs(nzB + idx + 3 * 32);
        }
    }

    // tail loads (lane<4): quad index 2496..2499
    float4 tlA, tlB;
    if (lane < 4) {
        tlA = __ldcs(nzA + 2496 + lane);
        tlB = __ldcs(nzB + 2496 + lane);
    }

    // epilogue: consume j=75,76,77 (already loaded into A0..A2/B0..B2)
    {
        const int idx = 75 * 32 + lane;
        float4 t = st4[idx], yv = sy4[idx];
        consume1(A0, t, yv, aq, aq2, aqy);
        consume1(B0, t, yv, bq, bq2, bqy);
    }
    {
        const int idx = 76 * 32 + lane;
        float4 t = st4[idx], yv = sy4[idx];
        consume1(A1, t, yv, aq, aq2, aqy);
        consume1(B1, t, yv, bq, bq2, bqy);
    }
    {
        const int idx = 77 * 32 + lane;
        float4 t = st4[idx], yv = sy4[idx];
        consume1(A2, t, yv, aq, aq2, aqy);
        consume1(B2, t, yv, bq, bq2, bqy);
    }
    if (lane < 4) {
        const int idx = 2496 + lane;
        float4 t = st4[idx], yv = sy4[idx];
        consume1(tlA, t, yv, aq, aq2, aqy);
        consume1(tlB, t, yv, bq, bq2, bqy);
    }

    // warp-local reductions for both samples
    #pragma unroll
    for (int o = 16; o; o >>= 1) {
        aq  += __shfl_xor_sync(0xffffffffu, aq,  o);
        aq2 += __shfl_xor_sync(0xffffffffu, aq2, o);
        aqy += __shfl_xor_sync(0xffffffffu, aqy, o);
        bq  += __shfl_xor_sync(0xffffffffu, bq,  o);
        bq2 += __shfl_xor_sync(0xffffffffu, bq2, o);
        bqy += __shfl_xor_sync(0xffffffffu, bqy, o);
    }
    const float invA = __frcp_rn(aq);
    const float invB = __frcp_rn(bq);
    float acc = fmaf(invA * invA, aq2, fmaf(-2.0f * invA, aqy, sy2))
              + fmaf(invB * invB, bq2, fmaf(-2.0f * invB, bqy, sy2));

    // ---- block combine (single barrier) + fused grid reduction ----
    if (lane == 0) fin[warp] = acc;
    __syncthreads();
    if (tid == 0) {
        float tot = fin[0];
        #pragma unroll
        for (int w = 1; w < NWARPS; w++) tot += fin[w];
        g_partial[bid] = tot;
        __threadfence();
        unsigned t = atomicAdd(&g_ticket, 1u);
        is_last = (t == NCTAS - 1) ? 1 : 0;
    }
    __syncthreads();

    if (is_last) {
        if (tid < NCTAS) {                     // warps 0..7
            float v = __ldcg(&g_partial[tid]);
            #pragma unroll
            for (int o = 16; o; o >>= 1) v += __shfl_xor_sync(0xffffffffu, v, o);
            if (lane == 0) fin[warp] = v;
        }
        __syncthreads();
        if (tid == 0) {
            float tot = 0.0f;
            #pragma unroll
            for (int w = 0; w < NCTAS / 32; w++) tot += fin[w];
            out[0] = tot * (1.0f / ((float)S_DIM * (float)B_DIM * (float)D_DIM));
            g_ticket = 0u;                      // reset for next graph replay
        }
    }
}

extern "C" void kernel_launch(void* const* d_in, const int* in_sizes, int n_in,
                              void* d_out, int out_size)
{
    const float* theta = (const float*)d_in[0];  // [B, D]
    const float* y     = (const float*)d_in[1];  // [B, D]
    const float* noise = (const float*)d_in[2];  // [S, B, D]
    float* out = (float*)d_out;

    cudaFuncSetAttribute(pl_fused,
                         cudaFuncAttributeMaxDynamicSharedMemorySize,
                         SMEM_BYTES);
    pl_fused<<<NCTAS, THREADS, SMEM_BYTES>>>(theta, y, noise, out);
}

// round 10
// speedup vs baseline: 1.0387x; 1.0387x over previous
#include <cuda_runtime.h>

// S=64, B=128, D=10000 fixed by the reference.
#define D_DIM   10000
#define D4      2500
#define J_FULL  78            // 78*32 = 2496 float4; tail = 4 (lane<4); 78 = 6*13
#define S_DIM   64
#define B_DIM   128
#define THREADS 512
#define NWARPS  16
#define DEPTH   6
#define SMEM_BYTES (2 * D_DIM * sizeof(float))   // 80000 B

#define L2E 1.4426950408889634f

__device__ float    g_partial[B_DIM];
__device__ unsigned g_ticket;      // zero-init; reset by last CTA each launch

__device__ __forceinline__ float ex2f(float x) {
    float r;
    asm("ex2.approx.ftz.f32 %0, %1;" : "=f"(r) : "f"(x));
    return r;
}

// consume one quad (noise n, theta*log2e t, y yv) into one sample's accumulators
__device__ __forceinline__ void consume1(const float4& n, const float4& t,
                                         const float4& yv,
                                         float& sq, float& sq2, float& sqy)
{
    float qx = ex2f(fmaf(n.x, L2E, t.x));
    float qy = ex2f(fmaf(n.y, L2E, t.y));
    float qz = ex2f(fmaf(n.z, L2E, t.z));
    float qw = ex2f(fmaf(n.w, L2E, t.w));
    sq  += (qx + qy) + (qz + qw);
    sq2 = fmaf(qx, qx, sq2);   sq2 = fmaf(qy, qy, sq2);
    sq2 = fmaf(qz, qz, sq2);   sq2 = fmaf(qw, qw, sq2);
    sqy = fmaf(qx, yv.x, sqy); sqy = fmaf(qy, yv.y, sqy);
    sqy = fmaf(qz, yv.z, sqy); sqy = fmaf(qw, yv.w, sqy);
}

__global__ __launch_bounds__(THREADS, 1)   // 1 CTA/SM -> up to 128 regs/thread
void pl_fused(const float* __restrict__ theta,
              const float* __restrict__ y,
              const float* __restrict__ noise,
              float* __restrict__ out)
{
    extern __shared__ float sm[];          // [0,10000): theta_b*log2e  [10000,20000): y_b
    float* __restrict__ sth = sm;
    float* __restrict__ syy = sm + D_DIM;
    __shared__ float fin[NWARPS];
    __shared__ float s_sy2;
    __shared__ int   is_last;

    const int b    = blockIdx.x;
    const int tid  = threadIdx.x;
    const int lane = tid & 31;
    const int warp = tid >> 5;

    // ---- stage theta_b*log2e, y_b into shared; exact fp32 Sigma(y^2) ----
    float sy2p = 0.0f;
    {
        const float4* __restrict__ th4 = (const float4*)(theta + (size_t)b * D_DIM);
        const float4* __restrict__ yy4 = (const float4*)(y     + (size_t)b * D_DIM);
        float4* s_t = (float4*)sth;
        float4* s_y = (float4*)syy;
        for (int i = tid; i < D4; i += THREADS) {
            float4 t = __ldg(th4 + i);
            float4 v = __ldg(yy4 + i);
            sy2p = fmaf(v.x, v.x, sy2p);
            sy2p = fmaf(v.y, v.y, sy2p);
            sy2p = fmaf(v.z, v.z, sy2p);
            sy2p = fmaf(v.w, v.w, sy2p);
            t.x *= L2E; t.y *= L2E; t.z *= L2E; t.w *= L2E;
            s_t[i] = t;
            s_y[i] = v;
        }
    }
    #pragma unroll
    for (int o = 16; o; o >>= 1) sy2p += __shfl_xor_sync(0xffffffffu, sy2p, o);
    if (lane == 0) fin[warp] = sy2p;
    __syncthreads();
    if (tid == 0) {
        float t = fin[0];
        #pragma unroll
        for (int w = 1; w < NWARPS; w++) t += fin[w];
        s_sy2 = t;
    }
    __syncthreads();
    const float sy2 = s_sy2;

    const float4* __restrict__ st4 = (const float4*)sth;
    const float4* __restrict__ sy4 = (const float4*)syy;

    float acc = 0.0f;

    // ---- 2 rounds; each round: warp interleaves adjacent samples sA, sA+1 ----
    #pragma unroll 1
    for (int r = 0; r < 2; r++) {
        const int sA = r * 32 + 2 * warp;      // samples 2w,2w+1 then +32
        const float4* __restrict__ nzA =
            (const float4*)(noise + ((size_t)sA * B_DIM + b) * D_DIM);
        const float4* __restrict__ nzB = nzA + (size_t)B_DIM * D4;  // sample sA+1

        float aq = 0.0f, aq2 = 0.0f, aqy = 0.0f;
        float bq = 0.0f, bq2 = 0.0f, bqy = 0.0f;

        // rotating 6-deep pipeline per sample (12 live buffers)
        float4 A[DEPTH], Bb[DEPTH];
        #pragma unroll
        for (int k = 0; k < DEPTH; k++) {
            A[k]  = __ldcs(nzA + k * 32 + lane);
            Bb[k] = __ldcs(nzB + k * 32 + lane);
        }

        // 12 blocks: consume j=jj..jj+5, reload j+6  (last reload = 72..77)
        #pragma unroll 1
        for (int jj = 0; jj <= 66; jj += 6) {
            #pragma unroll
            for (int k = 0; k < DEPTH; k++) {
                const int idx = (jj + k) * 32 + lane;
                float4 t = st4[idx], yv = sy4[idx];
                consume1(A[k],  t, yv, aq, aq2, aqy);
                consume1(Bb[k], t, yv, bq, bq2, bqy);
                A[k]  = __ldcs(nzA + idx + DEPTH * 32);
                Bb[k] = __ldcs(nzB + idx + DEPTH * 32);
            }
        }

        // tail loads (lane<4): quad index 2496..2499, issued before epilogue
        float4 tlA, tlB;
        if (lane < 4) {
            tlA = __ldcs(nzA + 2496 + lane);
            tlB = __ldcs(nzB + 2496 + lane);
        }

        // epilogue: consume j=72..77 (already in A/Bb), no reloads
        #pragma unroll
        for (int k = 0; k < DEPTH; k++) {
            const int idx = (72 + k) * 32 + lane;
            float4 t = st4[idx], yv = sy4[idx];
            consume1(A[k],  t, yv, aq, aq2, aqy);
            consume1(Bb[k], t, yv, bq, bq2, bqy);
        }
        if (lane < 4) {
            const int idx = 2496 + lane;
            float4 t = st4[idx], yv = sy4[idx];
            consume1(tlA, t, yv, aq, aq2, aqy);
            consume1(tlB, t, yv, bq, bq2, bqy);
        }

        // warp-local reductions for both samples
        #pragma unroll
        for (int o = 16; o; o >>= 1) {
            aq  += __shfl_xor_sync(0xffffffffu, aq,  o);
            aq2 += __shfl_xor_sync(0xffffffffu, aq2, o);
            aqy += __shfl_xor_sync(0xffffffffu, aqy, o);
            bq  += __shfl_xor_sync(0xffffffffu, bq,  o);
            bq2 += __shfl_xor_sync(0xffffffffu, bq2, o);
            bqy += __shfl_xor_sync(0xffffffffu, bqy, o);
        }
        const float invA = __frcp_rn(aq);
        const float invB = __frcp_rn(bq);
        acc += fmaf(invA * invA, aq2, fmaf(-2.0f * invA, aqy, sy2))
             + fmaf(invB * invB, bq2, fmaf(-2.0f * invB, bqy, sy2));
    }

    // ---- block combine (single barrier) + fused grid reduction ----
    if (lane == 0) fin[warp] = acc;
    __syncthreads();
    if (tid == 0) {
        float tot = fin[0];
        #pragma unroll
        for (int w = 1; w < NWARPS; w++) tot += fin[w];
        g_partial[b] = tot;
        __threadfence();
        unsigned t = atomicAdd(&g_ticket, 1u);
        is_last = (t == B_DIM - 1) ? 1 : 0;
    }
    __syncthreads();

    if (is_last) {
        if (tid < B_DIM) {                     // warps 0..3
            float v = __ldcg(&g_partial[tid]);
            #pragma unroll
            for (int o = 16; o; o >>= 1) v += __shfl_xor_sync(0xffffffffu, v, o);
            if (lane == 0) fin[warp] = v;
        }
        __syncthreads();
        if (tid == 0) {
            float tot = fin[0] + fin[1] + fin[2] + fin[3];
            out[0] = tot * (1.0f / ((float)S_DIM * (float)B_DIM * (float)D_DIM));
            g_ticket = 0u;                      // reset for next graph replay
        }
    }
}

extern "C" void kernel_launch(void* const* d_in, const int* in_sizes, int n_in,
                              void* d_out, int out_size)
{
    const float* theta = (const float*)d_in[0];  // [B, D]
    const float* y     = (const float*)d_in[1];  // [B, D]
    const float* noise = (const float*)d_in[2];  // [S, B, D]
    float* out = (float*)d_out;

    cudaFuncSetAttribute(pl_fused,
                         cudaFuncAttributeMaxDynamicSharedMemorySize,
                         SMEM_BYTES);
    pl_fused<<<B_DIM, THREADS, SMEM_BYTES>>>(theta, y, noise, out);
}

// round 11
// speedup vs baseline: 1.0399x; 1.0012x over previous
#include <cuda_runtime.h>

// S=64, B=128, D=10000 fixed by the reference.
#define D_DIM   10000
#define D4      2500
#define J_FULL  78            // 78*32 = 2496 float4; tail = 4 (lane<4); 78 = 6*13
#define S_DIM   64
#define B_DIM   128
#define THREADS 512
#define NWARPS  16
#define DEPTH   6
#define SMEM_BYTES (2 * D_DIM * sizeof(float))   // 80000 B

#define L2E 1.4426950408889634f

__device__ float    g_partial[B_DIM];
__device__ unsigned g_ticket;      // zero-init; reset by last CTA each launch

__device__ __forceinline__ float ex2f(float x) {
    float r;
    asm("ex2.approx.ftz.f32 %0, %1;" : "=f"(r) : "f"(x));
    return r;
}

// consume one quad (noise n, theta*log2e t, y yv) into one sample's accumulators
__device__ __forceinline__ void consume1(const float4& n, const float4& t,
                                         const float4& yv,
                                         float& sq, float& sq2, float& sqy)
{
    float qx = ex2f(fmaf(n.x, L2E, t.x));
    float qy = ex2f(fmaf(n.y, L2E, t.y));
    float qz = ex2f(fmaf(n.z, L2E, t.z));
    float qw = ex2f(fmaf(n.w, L2E, t.w));
    sq  += (qx + qy) + (qz + qw);
    sq2 = fmaf(qx, qx, sq2);   sq2 = fmaf(qy, qy, sq2);
    sq2 = fmaf(qz, qz, sq2);   sq2 = fmaf(qw, qw, sq2);
    sqy = fmaf(qx, yv.x, sqy); sqy = fmaf(qy, yv.y, sqy);
    sqy = fmaf(qz, yv.z, sqy); sqy = fmaf(qw, yv.w, sqy);
}

__global__ __launch_bounds__(THREADS, 1)   // 1 CTA/SM -> up to 128 regs/thread
void pl_fused(const float* __restrict__ theta,
              const float* __restrict__ y,
              const float* __restrict__ noise,
              float* __restrict__ out)
{
    extern __shared__ float sm[];          // [0,10000): theta_b*log2e  [10000,20000): y_b
    float* __restrict__ sth = sm;
    float* __restrict__ syy = sm + D_DIM;
    __shared__ float fin[NWARPS];
    __shared__ float s_sy2;
    __shared__ int   is_last;

    const int b    = blockIdx.x;
    const int tid  = threadIdx.x;
    const int lane = tid & 31;
    const int warp = tid >> 5;

    // ---- stage theta_b*log2e, y_b into shared; exact fp32 Sigma(y^2) ----
    float sy2p = 0.0f;
    {
        const float4* __restrict__ th4 = (const float4*)(theta + (size_t)b * D_DIM);
        const float4* __restrict__ yy4 = (const float4*)(y     + (size_t)b * D_DIM);
        float4* s_t = (float4*)sth;
        float4* s_y = (float4*)syy;
        for (int i = tid; i < D4; i += THREADS) {
            float4 t = __ldg(th4 + i);
            float4 v = __ldg(yy4 + i);
            sy2p = fmaf(v.x, v.x, sy2p);
            sy2p = fmaf(v.y, v.y, sy2p);
            sy2p = fmaf(v.z, v.z, sy2p);
            sy2p = fmaf(v.w, v.w, sy2p);
            t.x *= L2E; t.y *= L2E; t.z *= L2E; t.w *= L2E;
            s_t[i] = t;
            s_y[i] = v;
        }
    }
    #pragma unroll
    for (int o = 16; o; o >>= 1) sy2p += __shfl_xor_sync(0xffffffffu, sy2p, o);
    if (lane == 0) fin[warp] = sy2p;
    __syncthreads();
    if (tid == 0) {
        float t = fin[0];
        #pragma unroll
        for (int w = 1; w < NWARPS; w++) t += fin[w];
        s_sy2 = t;
    }
    __syncthreads();
    const float sy2 = s_sy2;

    const float4* __restrict__ st4 = (const float4*)sth;
    const float4* __restrict__ sy4 = (const float4*)syy;

    float acc = 0.0f;

    // ---- 2 rounds; each round: warp interleaves adjacent samples sA, sA+1 ----
    #pragma unroll 1
    for (int r = 0; r < 2; r++) {
        const int sA = r * 32 + 2 * warp;      // samples 2w,2w+1 then +32
        const float4* __restrict__ nzA =
            (const float4*)(noise + ((size_t)sA * B_DIM + b) * D_DIM);
        const float4* __restrict__ nzB = nzA + (size_t)B_DIM * D4;  // sample sA+1

        float aq = 0.0f, aq2 = 0.0f, aqy = 0.0f;
        float bq = 0.0f, bq2 = 0.0f, bqy = 0.0f;

        // rotating 6-deep pipeline per sample (12 live buffers)
        float4 A[DEPTH], Bb[DEPTH];
        #pragma unroll
        for (int k = 0; k < DEPTH; k++) {
            A[k]  = __ldcs(nzA + k * 32 + lane);
            Bb[k] = __ldcs(nzB + k * 32 + lane);
        }

        // 12 blocks: consume j=jj..jj+5, reload j+6  (last reload = 72..77)
        #pragma unroll 1
        for (int jj = 0; jj <= 66; jj += 6) {
            #pragma unroll
            for (int k = 0; k < DEPTH; k++) {
                const int idx = (jj + k) * 32 + lane;
                float4 t = st4[idx], yv = sy4[idx];
                consume1(A[k],  t, yv, aq, aq2, aqy);
                consume1(Bb[k], t, yv, bq, bq2, bqy);
                A[k]  = __ldcs(nzA + idx + DEPTH * 32);
                Bb[k] = __ldcs(nzB + idx + DEPTH * 32);
            }
        }

        // tail loads (lane<4): quad index 2496..2499, issued before epilogue
        float4 tlA, tlB;
        if (lane < 4) {
            tlA = __ldcs(nzA + 2496 + lane);
            tlB = __ldcs(nzB + 2496 + lane);
        }

        // epilogue: consume j=72..77 (already in A/Bb), no reloads
        #pragma unroll
        for (int k = 0; k < DEPTH; k++) {
            const int idx = (72 + k) * 32 + lane;
            float4 t = st4[idx], yv = sy4[idx];
            consume1(A[k],  t, yv, aq, aq2, aqy);
            consume1(Bb[k], t, yv, bq, bq2, bqy);
        }
        if (lane < 4) {
            const int idx = 2496 + lane;
            float4 t = st4[idx], yv = sy4[idx];
            consume1(tlA, t, yv, aq, aq2, aqy);
            consume1(tlB, t, yv, bq, bq2, bqy);
        }

        // warp-local reductions for both samples
        #pragma unroll
        for (int o = 16; o; o >>= 1) {
            aq  += __shfl_xor_sync(0xffffffffu, aq,  o);
            aq2 += __shfl_xor_sync(0xffffffffu, aq2, o);
            aqy += __shfl_xor_sync(0xffffffffu, aqy, o);
            bq  += __shfl_xor_sync(0xffffffffu, bq,  o);
            bq2 += __shfl_xor_sync(0xffffffffu, bq2, o);
            bqy += __shfl_xor_sync(0xffffffffu, bqy, o);
        }
        const float invA = __frcp_rn(aq);
        const float invB = __frcp_rn(bq);
        acc += fmaf(invA * invA, aq2, fmaf(-2.0f * invA, aqy, sy2))
             + fmaf(invB * invB, bq2, fmaf(-2.0f * invB, bqy, sy2));
    }

    // ---- block combine (single barrier) + fused grid reduction ----
    if (lane == 0) fin[warp] = acc;
    __syncthreads();
    if (tid == 0) {
        float tot = fin[0];
        #pragma unroll
        for (int w = 1; w < NWARPS; w++) tot += fin[w];
        g_partial[b] = tot;
        __threadfence();
        unsigned t = atomicAdd(&g_ticket, 1u);
        is_last = (t == B_DIM - 1) ? 1 : 0;
    }
    __syncthreads();

    if (is_last) {
        if (tid < B_DIM) {                     // warps 0..3
            float v = __ldcg(&g_partial[tid]);
            #pragma unroll
            for (int o = 16; o; o >>= 1) v += __shfl_xor_sync(0xffffffffu, v, o);
            if (lane == 0) fin[warp] = v;
        }
        __syncthreads();
        if (tid == 0) {
            float tot = fin[0] + fin[1] + fin[2] + fin[3];
            out[0] = tot * (1.0f / ((float)S_DIM * (float)B_DIM * (float)D_DIM));
            g_ticket = 0u;                      // reset for next graph replay
        }
    }
}

extern "C" void kernel_launch(void* const* d_in, const int* in_sizes, int n_in,
                              void* d_out, int out_size)
{
    const float* theta = (const float*)d_in[0];  // [B, D]
    const float* y     = (const float*)d_in[1];  // [B, D]
    const float* noise = (const float*)d_in[2];  // [S, B, D]
    float* out = (float*)d_out;

    cudaFuncSetAttribute(pl_fused,
                         cudaFuncAttributeMaxDynamicSharedMemorySize,
                         SMEM_BYTES);
    pl_fused<<<B_DIM, THREADS, SMEM_BYTES>>>(theta, y, noise, out);
}